// round 10
// baseline (speedup 1.0000x reference)
#include <cuda_runtime.h>
#include <cuda_bf16.h>
#include <math.h>

#define Bb 32
#define Ss 512
#define Hh 1024
#define Mm 8
#define NTOK (Bb * Ss)       // 16384
#define NSPAN (NTOK * Mm)    // 131072
#define TOPK 4915            // int(0.3 * B * S)
#define NBIN 65536
#define NCHUNK 1024          // 64 bins per chunk
#define TIE_CAP 16384
#define NB 148               // blocks == SMs (all co-resident)
#define NT 1024

// ---------------- device scratch ----------------
__device__ float g_query[Hh];
__device__ float g_e[NTOK];
__device__ float g_f[NTOK];
__device__ unsigned int g_keys[NSPAN];
__device__ int   g_hist16[NBIN];
__device__ int   g_chunk[NCHUNK];
__device__ unsigned char g_gbits[NTOK];
__device__ float g_sp_sum;
__device__ int   g_gold_cnt;
__device__ int   g_valid_cnt;
__device__ int   g_right;
__device__ int   g_tiecnt;
__device__ int   g_tie[TIE_CAP];
__device__ int   g_barcnt[8];          // zero-initialized; monotonic across replays

__device__ __forceinline__ float warpReduceF(float v) {
    #pragma unroll
    for (int o = 16; o; o >>= 1) v += __shfl_xor_sync(0xffffffffu, v, o);
    return v;
}
__device__ __forceinline__ int warpReduceI(int v) {
    #pragma unroll
    for (int o = 16; o; o >>= 1) v += __shfl_xor_sync(0xffffffffu, v, o);
    return v;
}

// Replay-safe grid barrier: counters only increase; target derived from arrival value.
__device__ __forceinline__ void grid_barrier(int i) {
    __syncthreads();
    if (threadIdx.x == 0) {
        __threadfence();
        int v = atomicAdd(&g_barcnt[i], 1);
        int target = (v / NB + 1) * NB;
        volatile int* p = &g_barcnt[i];
        while (*p < target) { __nanosleep(32); }
        __threadfence();
    }
    __syncthreads();
}

__global__ void __launch_bounds__(NT, 1)
k_all(const float* __restrict__ hidden,
      const float* __restrict__ tw,
      const float* __restrict__ w_in,
      const float* __restrict__ b_in,
      const float* __restrict__ score_w,
      const float* __restrict__ score_b_p,
      const int*   __restrict__ seq_len,
      const int*   __restrict__ gold_mask,
      float*       __restrict__ out) {
    __shared__ float shA[Hh];
    __shared__ float shB[Hh];
    __shared__ int   sch[NCHUNK];
    __shared__ int   s_bins[64];
    __shared__ int   s_bc, s_above;
    __shared__ int   shc[32];
    __shared__ float shf[32];
    __shared__ int   shg[32], shv[32];

    int tid = threadIdx.x;
    int bid = blockIdx.x;
    int warp = tid >> 5, lane = tid & 31;
    int gid = bid * NT + tid;

    // ---- Phase A: init scalars, zero histogram, stage tw ----
    if (gid == 0) {
        g_sp_sum = 0.0f; g_gold_cnt = 0; g_valid_cnt = 0;
        g_right = 0; g_tiecnt = 0;
    }
    if (gid < NBIN) g_hist16[gid] = 0;      // blocks 0..63 cover all bins
    shA[tid] = tw[tid];                      // NT == Hh
    __syncthreads();

    // ---- Phase A2: query rows (7 rows per block, warp-per-row; warp-uniform guard) ----
    {
        int r = bid * 7 + warp;
        if (warp < 7 && r < Hh) {
            const float4* wr = reinterpret_cast<const float4*>(w_in + (size_t)r * Hh);
            const float4* t4 = reinterpret_cast<const float4*>(shA);
            float acc = 0.0f;
            #pragma unroll
            for (int c = 0; c < 8; c++) {
                int j = c * 32 + lane;
                float4 a = wr[j]; float4 b = t4[j];
                acc += a.x * b.x + a.y * b.y + a.z * b.z + a.w * b.w;
            }
            acc = warpReduceF(acc);
            if (lane == 0) g_query[r] = acc + b_in[r];
        }
    }
    grid_barrier(0);

    // ---- Phase B: e/f dot products (warp-per-token, 64MB DRAM pass) ----
    shA[tid] = g_query[tid];
    shB[tid] = score_w[tid];
    __syncthreads();
    {
        int gw = bid * 32 + warp;            // 0..4735
        for (int t = gw; t < NTOK; t += NB * 32) {   // warp-uniform trip count
            const float4* hp = reinterpret_cast<const float4*>(hidden + (size_t)t * Hh);
            float e = 0.0f, f = 0.0f;
            #pragma unroll
            for (int c = 0; c < 8; c++) {
                int j = c * 32 + lane;
                float4 h = hp[j];
                int k = j * 4;
                e += h.x * shA[k] + h.y * shA[k + 1] + h.z * shA[k + 2] + h.w * shA[k + 3];
                f += h.x * shB[k] + h.y * shB[k + 1] + h.z * shB[k + 2] + h.w * shB[k + 3];
            }
            e = warpReduceF(e);
            f = warpReduceF(f);
            if (lane == 0) { g_e[t] = e; g_f[t] = f; }
        }
    }
    grid_barrier(1);

    // ---- Phase C: scores + keys + gbits + histogram + loss accumulators ----
    {
        float sp_local = 0.0f;
        int gold_local = 0, valid_local = 0;
        int t = bid * 111 + tid;             // 148*111 = 16428 >= 16384
        if (tid < 111 && t < NTOK) {         // no warp-collectives inside
            int b = t >> 9, s = t & (Ss - 1);
            int L = seq_len[b];
            float sb = score_b_p[0];

            const int4* gm4 = reinterpret_cast<const int4*>(gold_mask + t * Mm);
            int4 gm0 = gm4[0], gm1 = gm4[1];
            int gm[8] = {gm0.x, gm0.y, gm0.z, gm0.w, gm1.x, gm1.y, gm1.z, gm1.w};

            float m = -INFINITY, den = 0.0f, num = 0.0f;
            unsigned keys[8];
            unsigned char gb = 0;
            #pragma unroll
            for (int l = 0; l < Mm; l++) {
                int pos = s + l; if (pos > Ss - 1) pos = Ss - 1;
                float el = g_e[(b << 9) + pos];
                float fl = g_f[(b << 9) + pos];
                float mn = fmaxf(m, el);
                float sc = expf(m - mn);
                float we = expf(el - mn);
                den = den * sc + we;
                num = num * sc + we * fl;
                m = mn;
                float score = num / den + sb;

                unsigned key;
                if (s + l + 1 <= L) {
                    unsigned u = __float_as_uint(score);
                    key = u ^ ((u >> 31) ? 0xFFFFFFFFu : 0x80000000u);
                    valid_local++;
                    if (gm[l] == 0) {
                        gold_local++;
                        gb |= (unsigned char)(1u << l);
                        sp_local += fmaxf(-score, 0.0f) + log1pf(expf(-fabsf(score)));
                    }
                } else {
                    key = 0x007FFFFFu;       // flipped -inf
                }
                keys[l] = key;
                atomicAdd(&g_hist16[key >> 16], 1);
            }
            uint4* kp = reinterpret_cast<uint4*>(g_keys + t * Mm);
            kp[0] = make_uint4(keys[0], keys[1], keys[2], keys[3]);
            kp[1] = make_uint4(keys[4], keys[5], keys[6], keys[7]);
            g_gbits[t] = gb;
        }
        // collectives executed by ALL threads
        float sp = warpReduceF(sp_local);
        int gd = warpReduceI(gold_local);
        int vd = warpReduceI(valid_local);
        if (lane == 0) { shf[warp] = sp; shg[warp] = gd; shv[warp] = vd; }
        __syncthreads();
        if (tid == 0) {
            float S1 = 0.0f; int S2 = 0, S3 = 0;
            #pragma unroll
            for (int w = 0; w < 32; w++) { S1 += shf[w]; S2 += shg[w]; S3 += shv[w]; }
            if (S2 | S3) { atomicAdd(&g_gold_cnt, S2); atomicAdd(&g_valid_cnt, S3); }
            if (S1 != 0.0f) atomicAdd(&g_sp_sum, S1);
        }
    }
    grid_barrier(2);

    // ---- Phase D: reduce hist -> 1024 chunk sums (shuffle hoisted: all lanes participate) ----
    {
        int gi = bid * 112 + tid;            // int4 index (4 bins each)
        bool act = (tid < 112 && gi < 16384);
        int s = 0;
        if (act) {
            const int4* h4 = reinterpret_cast<const int4*>(g_hist16);
            int4 v = h4[gi];
            s = v.x + v.y + v.z + v.w;
        }
        #pragma unroll
        for (int o = 8; o; o >>= 1) s += __shfl_xor_sync(0xffffffffu, s, o);  // 16-lane groups
        if (act && (tid & 15) == 0) g_chunk[gi >> 4] = s;
    }
    grid_barrier(3);

    // ---- Phase E: redundant per-block suffix scan + boundary walk ----
    {
        int csum = g_chunk[tid];
        sch[tid] = csum;
        __syncthreads();
        for (int off = 1; off < NCHUNK; off <<= 1) {
            int v = (tid + off < NCHUNK) ? sch[tid + off] : 0;
            __syncthreads();
            sch[tid] += v;
            __syncthreads();
        }
        int incl = sch[tid];
        int above = incl - csum;
        if (above < TOPK && incl >= TOPK) { s_bc = tid; s_above = above; }
        __syncthreads();
        int bc = s_bc;
        if (tid < 64) s_bins[tid] = g_hist16[bc * 64 + tid];
        __syncthreads();
        if (tid == 0) {
            int cum = s_above;
            for (int bn = 63; bn >= 0; bn--) {
                int c = s_bins[bn];
                if (cum + c >= TOPK) {
                    s_bc = bc * 64 + bn;     // selP
                    s_above = TOPK - cum;    // rem
                    break;
                }
                cum += c;
            }
        }
        __syncthreads();
    }
    unsigned P = (unsigned)s_bc;
    int rem = s_above;

    // ---- Phase F: count gold above threshold + collect ties ----
    {
        int gg = 0;
        if (gid < NSPAN) {
            unsigned top = g_keys[gid] >> 16;
            if (top > P) {
                if ((g_gbits[gid >> 3] >> (gid & 7)) & 1) gg++;
            } else if (top == P) {
                int pos = atomicAdd(&g_tiecnt, 1);
                if (pos < TIE_CAP) g_tie[pos] = gid;
            }
        }
        gg = warpReduceI(gg);                // all threads participate
        if (lane == 0) shc[warp] = gg;
        __syncthreads();
        if (tid == 0) {
            int S = 0;
            #pragma unroll
            for (int w = 0; w < 32; w++) S += shc[w];
            if (S) atomicAdd(&g_right, S);
        }
    }
    grid_barrier(4);

    // ---- Phase G: block 0 ranks ties and writes outputs ----
    if (bid == 0) {
        int n = g_tiecnt; if (n > TIE_CAP) n = TIE_CAP;
        __shared__ int s_g;
        if (tid == 0) s_g = 0;
        __syncthreads();

        int gtie = 0;
        for (int j = tid; j < n; j += NT) {
            int ij = g_tie[j];
            unsigned kj = g_keys[ij];
            int rank = 0;
            for (int q = 0; q < n; q++) {
                int iq = g_tie[q];
                unsigned kq = g_keys[iq];
                if (kq > kj || (kq == kj && iq < ij)) rank++;
            }
            if (rank < rem) {
                if ((g_gbits[ij >> 3] >> (ij & 7)) & 1) gtie++;
            }
        }
        gtie = warpReduceI(gtie);            // all threads of block 0
        if (lane == 0 && gtie) atomicAdd(&s_g, gtie);
        __syncthreads();

        if (tid == 0) {
            int right = g_right + s_g;
            float nv = (float)g_valid_cnt;
            float loss = (g_sp_sum + 0.6931471805599453f * (float)(g_valid_cnt - g_gold_cnt)) / nv;
            out[0] = loss;
            out[1] = (float)right / (float)TOPK;
        }
    }
}

// ---------------- launch ----------------
extern "C" void kernel_launch(void* const* d_in, const int* in_sizes, int n_in,
                              void* d_out, int out_size) {
    const float* hidden  = (const float*)d_in[0];
    const float* tw      = (const float*)d_in[1];
    const float* w_in    = (const float*)d_in[2];
    const float* b_in    = (const float*)d_in[3];
    const float* score_w = (const float*)d_in[4];
    const float* score_b = (const float*)d_in[5];
    const int*   seq_len = (const int*)d_in[6];
    const int*   gold    = (const int*)d_in[7];
    float* out = (float*)d_out;

    k_all<<<NB, NT>>>(hidden, tw, w_in, b_in, score_w, score_b, seq_len, gold, out);
}

// round 11
// speedup vs baseline: 1.4992x; 1.4992x over previous
#include <cuda_runtime.h>
#include <cuda_bf16.h>
#include <math.h>

#define Bb 32
#define Ss 512
#define Hh 1024
#define Mm 8
#define NTOK (Bb * Ss)       // 16384
#define NSPAN (NTOK * Mm)    // 131072
#define TOPK 4915            // int(0.3 * B * S)
#define NBIN 65536
#define NCHUNK 1024          // 64 bins per chunk
#define TIE_CAP 16384

// ---------------- device scratch ----------------
__device__ float g_query[Hh];
__device__ float g_e[NTOK];
__device__ float g_f[NTOK];
__device__ unsigned int g_keys[NSPAN];
__device__ int   g_hist16[NBIN];
__device__ int   g_chunk[NCHUNK];
__device__ unsigned char g_gbits[NTOK];   // bit l of byte t: span (t,l) valid&&gold
__device__ float g_sp_sum;
__device__ int   g_gold_cnt;
__device__ int   g_valid_cnt;
__device__ int   g_right;
__device__ int   g_tiecnt;
__device__ int   g_done;
__device__ int   g_tie[TIE_CAP];

__device__ __forceinline__ float warpReduceF(float v) {
    #pragma unroll
    for (int o = 16; o; o >>= 1) v += __shfl_xor_sync(0xffffffffu, v, o);
    return v;
}
__device__ __forceinline__ int warpReduceI(int v) {
    #pragma unroll
    for (int o = 16; o; o >>= 1) v += __shfl_xor_sync(0xffffffffu, v, o);
    return v;
}

// ---------------- kernel 1: query = w_in @ term_weight + b_in; init state ----------------
__global__ void k_query(const float* __restrict__ w_in,
                        const float* __restrict__ tw,
                        const float* __restrict__ b_in) {
    int r = blockIdx.x;
    if (r == 0 && threadIdx.x == 0) {
        g_sp_sum = 0.0f; g_gold_cnt = 0; g_valid_cnt = 0;
        g_right = 0; g_tiecnt = 0; g_done = 0;
    }
    const float4* wr = reinterpret_cast<const float4*>(w_in + (size_t)r * Hh);
    const float4* t4 = reinterpret_cast<const float4*>(tw);
    int i = threadIdx.x;
    float4 a = wr[i];
    float4 b = t4[i];
    float acc = a.x * b.x + a.y * b.y + a.z * b.z + a.w * b.w;

    __shared__ float sh[8];
    float v = warpReduceF(acc);
    if ((threadIdx.x & 31) == 0) sh[threadIdx.x >> 5] = v;
    __syncthreads();
    if (threadIdx.x < 8) {
        float x = sh[threadIdx.x];
        #pragma unroll
        for (int o = 4; o; o >>= 1) x += __shfl_xor_sync(0xffu, x, o);
        if (threadIdx.x == 0) g_query[r] = x + b_in[r];
    }
}

// ---------------- kernel 2: e/f dot products; also zeroes hist ----------------
__global__ void k_ef(const float* __restrict__ hidden,
                     const float* __restrict__ score_w) {
    __shared__ float shq[Hh];
    __shared__ float shw[Hh];
    int gid = blockIdx.x * blockDim.x + threadIdx.x;
    if (gid < NBIN) g_hist16[gid] = 0;
    for (int i = threadIdx.x; i < Hh; i += blockDim.x) {
        shq[i] = g_query[i];
        shw[i] = score_w[i];
    }
    __syncthreads();

    int warp = threadIdx.x >> 5, lane = threadIdx.x & 31;
    int t = blockIdx.x * 8 + warp;
    const float4* hp = reinterpret_cast<const float4*>(hidden + (size_t)t * Hh);
    float e = 0.0f, f = 0.0f;
    #pragma unroll
    for (int c = 0; c < 8; c++) {
        int j = c * 32 + lane;
        float4 h = hp[j];
        int k = j * 4;
        e += h.x * shq[k] + h.y * shq[k + 1] + h.z * shq[k + 2] + h.w * shq[k + 3];
        f += h.x * shw[k] + h.y * shw[k + 1] + h.z * shw[k + 2] + h.w * shw[k + 3];
    }
    e = warpReduceF(e);
    f = warpReduceF(f);
    if (lane == 0) { g_e[t] = e; g_f[t] = f; }
}

// ---------------- kernel 3: scores, keys, gold bits, loss accum, 16-bit histogram ----------------
__global__ void k_scores(const float* __restrict__ score_b_p,
                         const int* __restrict__ seq_len,
                         const int* __restrict__ gold_mask) {
    int t = blockIdx.x * blockDim.x + threadIdx.x;
    float sp_local = 0.0f;
    int gold_local = 0, valid_local = 0;

    if (t < NTOK) {
        int b = t >> 9, s = t & (Ss - 1);
        int L = seq_len[b];
        float sb = score_b_p[0];

        const int4* gm4 = reinterpret_cast<const int4*>(gold_mask + t * Mm);
        int4 gm0 = gm4[0], gm1 = gm4[1];
        int gm[8] = {gm0.x, gm0.y, gm0.z, gm0.w, gm1.x, gm1.y, gm1.z, gm1.w};

        float m = -INFINITY, den = 0.0f, num = 0.0f;
        unsigned keys[8];
        unsigned char gb = 0;
        #pragma unroll
        for (int l = 0; l < Mm; l++) {
            int pos = s + l; if (pos > Ss - 1) pos = Ss - 1;
            float el = g_e[(b << 9) + pos];
            float fl = g_f[(b << 9) + pos];
            float mn = fmaxf(m, el);
            float sc = expf(m - mn);
            float we = expf(el - mn);
            den = den * sc + we;
            num = num * sc + we * fl;
            m = mn;
            float score = num / den + sb;

            unsigned key;
            if (s + l + 1 <= L) {
                unsigned u = __float_as_uint(score);
                key = u ^ ((u >> 31) ? 0xFFFFFFFFu : 0x80000000u);
                valid_local++;
                if (gm[l] == 0) {
                    gold_local++;
                    gb |= (unsigned char)(1u << l);
                    sp_local += fmaxf(-score, 0.0f) + log1pf(expf(-fabsf(score)));
                }
            } else {
                key = 0x007FFFFFu;  // flipped -inf
            }
            keys[l] = key;
            atomicAdd(&g_hist16[key >> 16], 1);
        }
        uint4* kp = reinterpret_cast<uint4*>(g_keys + t * Mm);
        kp[0] = make_uint4(keys[0], keys[1], keys[2], keys[3]);
        kp[1] = make_uint4(keys[4], keys[5], keys[6], keys[7]);
        g_gbits[t] = gb;
    }

    __shared__ float shf[8];
    __shared__ int shg[8], shv[8];
    float sp = warpReduceF(sp_local);
    int gd = warpReduceI(gold_local);
    int vd = warpReduceI(valid_local);
    if ((threadIdx.x & 31) == 0) {
        int w = threadIdx.x >> 5;
        shf[w] = sp; shg[w] = gd; shv[w] = vd;
    }
    __syncthreads();
    if (threadIdx.x == 0) {
        float S1 = 0.0f; int S2 = 0, S3 = 0;
        #pragma unroll
        for (int w = 0; w < 8; w++) { S1 += shf[w]; S2 += shg[w]; S3 += shv[w]; }
        atomicAdd(&g_sp_sum, S1);
        atomicAdd(&g_gold_cnt, S2);
        atomicAdd(&g_valid_cnt, S3);
    }
}

// ---------------- kernel 4: grid-parallel vectorized reduce 65536 bins -> 1024 chunk sums ----
__global__ void k_reduce() {
    int tid = threadIdx.x;
    int gt = blockIdx.x * 1024 + tid;        // int4 index; covers 4 bins
    const int4* h4 = reinterpret_cast<const int4*>(g_hist16);
    int4 v = h4[gt];                         // fully coalesced
    int s = v.x + v.y + v.z + v.w;
    #pragma unroll
    for (int o = 8; o; o >>= 1) s += __shfl_xor_sync(0xffffffffu, s, o);
    if ((tid & 15) == 0) g_chunk[gt >> 4] = s;
}

// ---------------- kernel 5: redundant per-block scan -> P,rem; vectorized count; last block final
// 16 blocks x 1024 threads. Each thread handles 8 spans (one gbits byte, two uint4 key loads).
__global__ void __launch_bounds__(1024, 1)
k_scan_count_final(float* __restrict__ out) {
    __shared__ int sch[NCHUNK];
    __shared__ int s_bins[64];
    __shared__ int s_bc, s_above;
    __shared__ int shc[32];
    __shared__ bool s_last;

    int tid = threadIdx.x;
    // ---- redundant suffix scan (identical in every block; parallel across blocks) ----
    int csum = g_chunk[tid];
    sch[tid] = csum;
    __syncthreads();
    for (int off = 1; off < NCHUNK; off <<= 1) {
        int v = (tid + off < NCHUNK) ? sch[tid + off] : 0;
        __syncthreads();
        sch[tid] += v;
        __syncthreads();
    }
    int incl = sch[tid];
    int above = incl - csum;
    if (above < TOPK && incl >= TOPK) { s_bc = tid; s_above = above; }
    __syncthreads();
    int bc = s_bc;
    if (tid < 64) s_bins[tid] = g_hist16[bc * 64 + tid];
    __syncthreads();
    if (tid == 0) {
        int cum = s_above;
        for (int bn = 63; bn >= 0; bn--) {
            int c = s_bins[bn];
            if (cum + c >= TOPK) {
                s_bc = bc * 64 + bn;        // P
                s_above = TOPK - cum;       // rem
                break;
            }
            cum += c;
        }
    }
    __syncthreads();
    unsigned P = (unsigned)s_bc;
    int rem = s_above;

    // ---- vectorized count: token tg = gid (16*1024=16384 == NTOK) ----
    int tg = blockIdx.x * 1024 + tid;
    int gg = 0;
    {
        unsigned gb = g_gbits[tg];
        const uint4* kp = reinterpret_cast<const uint4*>(g_keys + tg * Mm);
        uint4 k0 = kp[0], k1 = kp[1];
        unsigned kk[8] = {k0.x, k0.y, k0.z, k0.w, k1.x, k1.y, k1.z, k1.w};
        #pragma unroll
        for (int l = 0; l < 8; l++) {
            unsigned top = kk[l] >> 16;
            if (top > P) {
                gg += (gb >> l) & 1;
            } else if (top == P) {
                int pos = atomicAdd(&g_tiecnt, 1);
                if (pos < TIE_CAP) g_tie[pos] = tg * Mm + l;
            }
        }
    }
    gg = warpReduceI(gg);
    if ((tid & 31) == 0) shc[tid >> 5] = gg;
    __syncthreads();
    if (tid == 0) {
        int S = 0;
        #pragma unroll
        for (int w = 0; w < 32; w++) S += shc[w];
        if (S) atomicAdd(&g_right, S);
        __threadfence();
        int d = atomicAdd(&g_done, 1);
        s_last = (d == (int)gridDim.x - 1);
    }
    __syncthreads();
    if (!s_last) return;

    // ---- final phase: only last block ----
    int n = g_tiecnt; if (n > TIE_CAP) n = TIE_CAP;
    __shared__ int s_g;
    if (tid == 0) s_g = 0;
    __syncthreads();

    int gtie = 0;
    for (int j = tid; j < n; j += 1024) {
        int ij = g_tie[j];
        unsigned kj = g_keys[ij];
        int rank = 0;
        for (int q = 0; q < n; q++) {
            int iq = g_tie[q];
            unsigned kq = g_keys[iq];
            if (kq > kj || (kq == kj && iq < ij)) rank++;
        }
        if (rank < rem) {
            if ((g_gbits[ij >> 3] >> (ij & 7)) & 1) gtie++;
        }
    }
    gtie = warpReduceI(gtie);
    if ((tid & 31) == 0 && gtie) atomicAdd(&s_g, gtie);
    __syncthreads();

    if (tid == 0) {
        int right = g_right + s_g;
        float nv = (float)g_valid_cnt;
        float loss = (g_sp_sum + 0.6931471805599453f * (float)(g_valid_cnt - g_gold_cnt)) / nv;
        out[0] = loss;
        out[1] = (float)right / (float)TOPK;
    }
}

// ---------------- launch ----------------
extern "C" void kernel_launch(void* const* d_in, const int* in_sizes, int n_in,
                              void* d_out, int out_size) {
    const float* hidden  = (const float*)d_in[0];
    const float* tw      = (const float*)d_in[1];
    const float* w_in    = (const float*)d_in[2];
    const float* b_in    = (const float*)d_in[3];
    const float* score_w = (const float*)d_in[4];
    const float* score_b = (const float*)d_in[5];
    const int*   seq_len = (const int*)d_in[6];
    const int*   gold    = (const int*)d_in[7];
    float* out = (float*)d_out;

    k_query           <<<Hh, 256>>>(w_in, tw, b_in);
    k_ef              <<<NTOK / 8, 256>>>(hidden, score_w);
    k_scores          <<<NTOK / 256, 256>>>(score_b, seq_len, gold);
    k_reduce          <<<16, 1024>>>();
    k_scan_count_final<<<16, 1024>>>(out);
}

// round 12
// speedup vs baseline: 1.5682x; 1.0460x over previous
#include <cuda_runtime.h>
#include <cuda_bf16.h>
#include <math.h>

#define Bb 32
#define Ss 512
#define Hh 1024
#define Mm 8
#define NTOK (Bb * Ss)       // 16384
#define NSPAN (NTOK * Mm)    // 131072
#define TOPK 4915            // int(0.3 * B * S)
#define NBIN 65536
#define NCHUNK 1024          // 64 bins per chunk
#define TIE_CAP 16384

// ---------------- device scratch ----------------
__device__ float g_query[Hh];
__device__ float g_e[NTOK];
__device__ float g_f[NTOK];
__device__ unsigned int g_keys[NSPAN];
__device__ int   g_hist16[NBIN];
__device__ int   g_chunk[NCHUNK];
__device__ unsigned char g_gbits[NTOK];   // bit l of byte t: span (t,l) valid&&gold
__device__ float g_sp_sum;
__device__ int   g_gold_cnt;
__device__ int   g_valid_cnt;
__device__ int   g_right;
__device__ int   g_tiecnt;
__device__ int   g_done;
__device__ int   g_tie[TIE_CAP];

__device__ __forceinline__ float warpReduceF(float v) {
    #pragma unroll
    for (int o = 16; o; o >>= 1) v += __shfl_xor_sync(0xffffffffu, v, o);
    return v;
}
__device__ __forceinline__ int warpReduceI(int v) {
    #pragma unroll
    for (int o = 16; o; o >>= 1) v += __shfl_xor_sync(0xffffffffu, v, o);
    return v;
}

// ---------------- kernel 1: query = w_in @ term_weight + b_in; init state ----------------
__global__ void k_query(const float* __restrict__ w_in,
                        const float* __restrict__ tw,
                        const float* __restrict__ b_in) {
    cudaTriggerProgrammaticLaunchCompletion();   // let k_ef launch + run its prologue early
    int r = blockIdx.x;
    if (r == 0 && threadIdx.x == 0) {
        g_sp_sum = 0.0f; g_gold_cnt = 0; g_valid_cnt = 0;
        g_right = 0; g_tiecnt = 0; g_done = 0;
    }
    const float4* wr = reinterpret_cast<const float4*>(w_in + (size_t)r * Hh);
    const float4* t4 = reinterpret_cast<const float4*>(tw);
    int i = threadIdx.x;
    float4 a = wr[i];
    float4 b = t4[i];
    float acc = a.x * b.x + a.y * b.y + a.z * b.z + a.w * b.w;

    __shared__ float sh[8];
    float v = warpReduceF(acc);
    if ((threadIdx.x & 31) == 0) sh[threadIdx.x >> 5] = v;
    __syncthreads();
    if (threadIdx.x < 8) {
        float x = sh[threadIdx.x];
        #pragma unroll
        for (int o = 4; o; o >>= 1) x += __shfl_xor_sync(0xffu, x, o);
        if (threadIdx.x == 0) g_query[r] = x + b_in[r];
    }
}

// ---------------- kernel 2: e/f dot products; also zeroes hist ----------------
__global__ void k_ef(const float* __restrict__ hidden,
                     const float* __restrict__ score_w) {
    cudaTriggerProgrammaticLaunchCompletion();
    __shared__ float shq[Hh];
    __shared__ float shw[Hh];
    // independent prologue (runs concurrent with k_query under PDL)
    int gid = blockIdx.x * blockDim.x + threadIdx.x;
    if (gid < NBIN) g_hist16[gid] = 0;
    for (int i = threadIdx.x; i < Hh; i += blockDim.x) shw[i] = score_w[i];
    // wait for k_query's g_query
    cudaGridDependencySynchronize();
    for (int i = threadIdx.x; i < Hh; i += blockDim.x) shq[i] = g_query[i];
    __syncthreads();

    int warp = threadIdx.x >> 5, lane = threadIdx.x & 31;
    int t = blockIdx.x * 8 + warp;
    const float4* hp = reinterpret_cast<const float4*>(hidden + (size_t)t * Hh);
    float e = 0.0f, f = 0.0f;
    #pragma unroll
    for (int c = 0; c < 8; c++) {
        int j = c * 32 + lane;
        float4 h = hp[j];
        int k = j * 4;
        e += h.x * shq[k] + h.y * shq[k + 1] + h.z * shq[k + 2] + h.w * shq[k + 3];
        f += h.x * shw[k] + h.y * shw[k + 1] + h.z * shw[k + 2] + h.w * shw[k + 3];
    }
    e = warpReduceF(e);
    f = warpReduceF(f);
    if (lane == 0) { g_e[t] = e; g_f[t] = f; }
}

// ---------------- kernel 3: scores, keys, gold bits, loss accum, 16-bit histogram ----------------
__global__ void k_scores(const float* __restrict__ score_b_p,
                         const int* __restrict__ seq_len,
                         const int* __restrict__ gold_mask) {
    cudaTriggerProgrammaticLaunchCompletion();
    int t = blockIdx.x * blockDim.x + threadIdx.x;
    float sp_local = 0.0f;
    int gold_local = 0, valid_local = 0;

    // independent prologue: pure-input loads (overlap with k_ef under PDL)
    int b = t >> 9, s = t & (Ss - 1);
    int L = seq_len[b];
    float sb = score_b_p[0];
    const int4* gm4 = reinterpret_cast<const int4*>(gold_mask + t * Mm);
    int4 gm0 = gm4[0], gm1 = gm4[1];
    int gm[8] = {gm0.x, gm0.y, gm0.z, gm0.w, gm1.x, gm1.y, gm1.z, gm1.w};

    // wait for k_ef's g_e/g_f (and its g_hist16 zeroing)
    cudaGridDependencySynchronize();

    if (t < NTOK) {
        float m = -INFINITY, den = 0.0f, num = 0.0f;
        unsigned keys[8];
        unsigned char gb = 0;
        #pragma unroll
        for (int l = 0; l < Mm; l++) {
            int pos = s + l; if (pos > Ss - 1) pos = Ss - 1;
            float el = g_e[(b << 9) + pos];
            float fl = g_f[(b << 9) + pos];
            float mn = fmaxf(m, el);
            float sc = expf(m - mn);
            float we = expf(el - mn);
            den = den * sc + we;
            num = num * sc + we * fl;
            m = mn;
            float score = num / den + sb;

            unsigned key;
            if (s + l + 1 <= L) {
                unsigned u = __float_as_uint(score);
                key = u ^ ((u >> 31) ? 0xFFFFFFFFu : 0x80000000u);
                valid_local++;
                if (gm[l] == 0) {
                    gold_local++;
                    gb |= (unsigned char)(1u << l);
                    sp_local += fmaxf(-score, 0.0f) + log1pf(expf(-fabsf(score)));
                }
            } else {
                key = 0x007FFFFFu;  // flipped -inf
            }
            keys[l] = key;
            atomicAdd(&g_hist16[key >> 16], 1);
        }
        uint4* kp = reinterpret_cast<uint4*>(g_keys + t * Mm);
        kp[0] = make_uint4(keys[0], keys[1], keys[2], keys[3]);
        kp[1] = make_uint4(keys[4], keys[5], keys[6], keys[7]);
        g_gbits[t] = gb;
    }

    __shared__ float shf[8];
    __shared__ int shg[8], shv[8];
    float sp = warpReduceF(sp_local);
    int gd = warpReduceI(gold_local);
    int vd = warpReduceI(valid_local);
    if ((threadIdx.x & 31) == 0) {
        int w = threadIdx.x >> 5;
        shf[w] = sp; shg[w] = gd; shv[w] = vd;
    }
    __syncthreads();
    if (threadIdx.x == 0) {
        float S1 = 0.0f; int S2 = 0, S3 = 0;
        #pragma unroll
        for (int w = 0; w < 8; w++) { S1 += shf[w]; S2 += shg[w]; S3 += shv[w]; }
        atomicAdd(&g_sp_sum, S1);
        atomicAdd(&g_gold_cnt, S2);
        atomicAdd(&g_valid_cnt, S3);
    }
}

// ---------------- kernel 4: grid-parallel vectorized reduce 65536 bins -> 1024 chunk sums ----
__global__ void k_reduce() {
    cudaTriggerProgrammaticLaunchCompletion();
    cudaGridDependencySynchronize();         // needs k_scores' g_hist16
    int tid = threadIdx.x;
    int gt = blockIdx.x * 1024 + tid;        // int4 index; covers 4 bins
    const int4* h4 = reinterpret_cast<const int4*>(g_hist16);
    int4 v = h4[gt];                         // fully coalesced
    int s = v.x + v.y + v.z + v.w;
    #pragma unroll
    for (int o = 8; o; o >>= 1) s += __shfl_xor_sync(0xffffffffu, s, o);
    if ((tid & 15) == 0) g_chunk[gt >> 4] = s;
}

// ---------------- kernel 5: redundant per-block scan -> P,rem; vectorized count; last block final
__global__ void __launch_bounds__(1024, 1)
k_scan_count_final(float* __restrict__ out) {
    __shared__ int sch[NCHUNK];
    __shared__ int s_bins[64];
    __shared__ int s_bc, s_above;
    __shared__ int shc[32];
    __shared__ bool s_last;

    cudaGridDependencySynchronize();         // needs k_reduce's g_chunk
    int tid = threadIdx.x;
    // ---- redundant suffix scan (identical in every block; parallel across blocks) ----
    int csum = g_chunk[tid];
    sch[tid] = csum;
    __syncthreads();
    for (int off = 1; off < NCHUNK; off <<= 1) {
        int v = (tid + off < NCHUNK) ? sch[tid + off] : 0;
        __syncthreads();
        sch[tid] += v;
        __syncthreads();
    }
    int incl = sch[tid];
    int above = incl - csum;
    if (above < TOPK && incl >= TOPK) { s_bc = tid; s_above = above; }
    __syncthreads();
    int bc = s_bc;
    if (tid < 64) s_bins[tid] = g_hist16[bc * 64 + tid];
    __syncthreads();
    if (tid == 0) {
        int cum = s_above;
        for (int bn = 63; bn >= 0; bn--) {
            int c = s_bins[bn];
            if (cum + c >= TOPK) {
                s_bc = bc * 64 + bn;        // P
                s_above = TOPK - cum;       // rem
                break;
            }
            cum += c;
        }
    }
    __syncthreads();
    unsigned P = (unsigned)s_bc;
    int rem = s_above;

    // ---- vectorized count: token tg = gid (16*1024=16384 == NTOK) ----
    int tg = blockIdx.x * 1024 + tid;
    int gg = 0;
    {
        unsigned gb = g_gbits[tg];
        const uint4* kp = reinterpret_cast<const uint4*>(g_keys + tg * Mm);
        uint4 k0 = kp[0], k1 = kp[1];
        unsigned kk[8] = {k0.x, k0.y, k0.z, k0.w, k1.x, k1.y, k1.z, k1.w};
        #pragma unroll
        for (int l = 0; l < 8; l++) {
            unsigned top = kk[l] >> 16;
            if (top > P) {
                gg += (gb >> l) & 1;
            } else if (top == P) {
                int pos = atomicAdd(&g_tiecnt, 1);
                if (pos < TIE_CAP) g_tie[pos] = tg * Mm + l;
            }
        }
    }
    gg = warpReduceI(gg);
    if ((tid & 31) == 0) shc[tid >> 5] = gg;
    __syncthreads();
    if (tid == 0) {
        int S = 0;
        #pragma unroll
        for (int w = 0; w < 32; w++) S += shc[w];
        if (S) atomicAdd(&g_right, S);
        __threadfence();
        int d = atomicAdd(&g_done, 1);
        s_last = (d == (int)gridDim.x - 1);
    }
    __syncthreads();
    if (!s_last) return;

    // ---- final phase: only last block ----
    int n = g_tiecnt; if (n > TIE_CAP) n = TIE_CAP;
    __shared__ int s_g;
    if (tid == 0) s_g = 0;
    __syncthreads();

    int gtie = 0;
    for (int j = tid; j < n; j += 1024) {
        int ij = g_tie[j];
        unsigned kj = g_keys[ij];
        int rank = 0;
        for (int q = 0; q < n; q++) {
            int iq = g_tie[q];
            unsigned kq = g_keys[iq];
            if (kq > kj || (kq == kj && iq < ij)) rank++;
        }
        if (rank < rem) {
            if ((g_gbits[ij >> 3] >> (ij & 7)) & 1) gtie++;
        }
    }
    gtie = warpReduceI(gtie);
    if ((tid & 31) == 0 && gtie) atomicAdd(&s_g, gtie);
    __syncthreads();

    if (tid == 0) {
        int right = g_right + s_g;
        float nv = (float)g_valid_cnt;
        float loss = (g_sp_sum + 0.6931471805599453f * (float)(g_valid_cnt - g_gold_cnt)) / nv;
        out[0] = loss;
        out[1] = (float)right / (float)TOPK;
    }
}

// ---------------- launch (PDL on all dependent nodes) ----------------
extern "C" void kernel_launch(void* const* d_in, const int* in_sizes, int n_in,
                              void* d_out, int out_size) {
    const float* hidden  = (const float*)d_in[0];
    const float* tw      = (const float*)d_in[1];
    const float* w_in    = (const float*)d_in[2];
    const float* b_in    = (const float*)d_in[3];
    const float* score_w = (const float*)d_in[4];
    const float* score_b = (const float*)d_in[5];
    const int*   seq_len = (const int*)d_in[6];
    const int*   gold    = (const int*)d_in[7];
    float* out = (float*)d_out;

    cudaLaunchAttribute at[1];
    at[0].id = cudaLaunchAttributeProgrammaticStreamSerialization;
    at[0].val.programmaticStreamSerializationAllowed = 1;

    // node 1: plain launch
    k_query<<<Hh, 256>>>(w_in, tw, b_in);

    // node 2: k_ef (PDL on k_query)
    {
        cudaLaunchConfig_t cfg = {};
        cfg.gridDim = dim3(NTOK / 8); cfg.blockDim = dim3(256);
        cfg.attrs = at; cfg.numAttrs = 1;
        cudaLaunchKernelEx(&cfg, k_ef, hidden, score_w);
    }
    // node 3: k_scores (PDL on k_ef)
    {
        cudaLaunchConfig_t cfg = {};
        cfg.gridDim = dim3(NTOK / 256); cfg.blockDim = dim3(256);
        cfg.attrs = at; cfg.numAttrs = 1;
        cudaLaunchKernelEx(&cfg, k_scores, score_b, seq_len, gold);
    }
    // node 4: k_reduce (PDL on k_scores)
    {
        cudaLaunchConfig_t cfg = {};
        cfg.gridDim = dim3(16); cfg.blockDim = dim3(1024);
        cfg.attrs = at; cfg.numAttrs = 1;
        cudaLaunchKernelEx(&cfg, k_reduce);
    }
    // node 5: k_scan_count_final (PDL on k_reduce)
    {
        cudaLaunchConfig_t cfg = {};
        cfg.gridDim = dim3(16); cfg.blockDim = dim3(1024);
        cfg.attrs = at; cfg.numAttrs = 1;
        cudaLaunchKernelEx(&cfg, k_scan_count_final, out);
    }
}